// round 3
// baseline (speedup 1.0000x reference)
#include <cuda_runtime.h>

#define B_  16
#define C_  64
#define N_  512
#define T_  64
#define OC_ 64

// ---------------- scratch (device globals; no runtime allocation) ----------
__device__ __align__(16) float g_norm [N_ * N_];
__device__ __align__(16) float g_norm2[N_ * N_];
__device__ __align__(16) float g_Z1[B_ * OC_ * N_ * T_];
__device__ __align__(16) float g_Z2[B_ * OC_ * N_ * T_];

// ---------------- packed f32x2 helpers (FFMA2: 2x fp32 rate) ---------------
__device__ __forceinline__ unsigned long long dup2(float v) {
    unsigned long long r;
    asm("mov.b64 %0, {%1, %1};" : "=l"(r) : "f"(v));
    return r;
}
__device__ __forceinline__ unsigned long long fma2(unsigned long long a,
                                                   unsigned long long b,
                                                   unsigned long long c) {
    unsigned long long d;
    asm("fma.rn.f32x2 %0, %1, %2, %3;" : "=l"(d) : "l"(a), "l"(b), "l"(c));
    return d;
}
__device__ __forceinline__ float2 up2(unsigned long long p) {
    float2 f;
    asm("mov.b64 {%0, %1}, %2;" : "=f"(f.x), "=f"(f.y) : "l"(p));
    return f;
}

// ---------------- kernel 0a: row-normalized adjacency -----------------------
__global__ void k_rownorm(const float* __restrict__ adj) {
    const int i = blockIdx.x;
    __shared__ float red[256];
    float s = 0.f;
    for (int j = threadIdx.x; j < N_; j += 256) s += adj[i * N_ + j];
    red[threadIdx.x] = s;
    __syncthreads();
    for (int off = 128; off > 0; off >>= 1) {
        if (threadIdx.x < off) red[threadIdx.x] += red[threadIdx.x + off];
        __syncthreads();
    }
    const float inv = 1.0f / (red[0] + 1e-6f);
    for (int j = threadIdx.x; j < N_; j += 256)
        g_norm[i * N_ + j] = adj[i * N_ + j] * inv;
}

// ---------------- kernel 0b: norm2 = norm @ norm (512^3, tiny) -------------
__global__ void k_norm2() {
    __shared__ float As[16][16];
    __shared__ float Bs[16][17];
    const int i = blockIdx.y * 16 + threadIdx.y;
    const int j = blockIdx.x * 16 + threadIdx.x;
    float acc = 0.f;
    for (int k0 = 0; k0 < N_; k0 += 16) {
        As[threadIdx.y][threadIdx.x] = g_norm[i * N_ + k0 + threadIdx.x];
        Bs[threadIdx.y][threadIdx.x] = g_norm[(k0 + threadIdx.y) * N_ + j];
        __syncthreads();
#pragma unroll
        for (int k = 0; k < 16; k++) acc += As[threadIdx.y][k] * Bs[k][threadIdx.x];
        __syncthreads();
    }
    g_norm2[i * N_ + j] = acc;
}

// ---------------- kernel 1: channel mix  Zk = X @ Wk^T  (K = 64) -----------
// block = (n, b). tile: 64 oc x 64 t. thread: 4 oc x 4 t per matrix, f32x2.
// Z0 (+bias) written directly into d_out; Z1/Z2 to scratch.
__global__ __launch_bounds__(256) void k_mix(const float* __restrict__ x,
                                             const float* __restrict__ W,
                                             const float* __restrict__ bias,
                                             float* __restrict__ z0) {
    __shared__ __align__(16) float Xs[32 * 64];   // [c'][t]
    __shared__ __align__(16) float Ws[96 * 64];   // [g*32+c'][oc], g in {0,1,2}
    const int n = blockIdx.x, b = blockIdx.y;
    const int tid = threadIdx.x;
    const int tx = tid & 15, ty = tid >> 4;
    const int t0 = tx * 4, oc0 = ty * 4;

    unsigned long long a0[4][2], a1[4][2], a2[4][2];
#pragma unroll
    for (int q = 0; q < 4; q++) {
        const unsigned long long bp = dup2(bias[oc0 + q]);
        a0[q][0] = bp;  a0[q][1] = bp;
        a1[q][0] = 0ull; a1[q][1] = 0ull;
        a2[q][0] = 0ull; a2[q][1] = 0ull;
    }

    for (int h = 0; h < 2; h++) {           // two c-halves of 32
        __syncthreads();
        // load X half: rows c' = 0..31, 64 contiguous t floats each
        for (int i2 = tid; i2 < 512; i2 += 256) {
            const int cc = i2 >> 4, q = (i2 & 15) * 4;
            *(float4*)(Xs + cc * 64 + q) =
                *(const float4*)(x + ((b * 64 + h * 32 + cc) * 512 + n) * 64 + q);
        }
        // load W half transposed: Ws[(g*32+cc)*64 + oc] = W[oc][g*64 + h*32 + cc]
        for (int i2 = tid; i2 < 6144; i2 += 256) {
            const int oc = i2 / 96, kk = i2 % 96;
            const int g = kk >> 5, cc = kk & 31;
            Ws[(g * 32 + cc) * 64 + oc] = W[oc * 192 + g * 64 + h * 32 + cc];
        }
        __syncthreads();
#pragma unroll 4
        for (int cc = 0; cc < 32; cc++) {
            const ulonglong2 xp = *(const ulonglong2*)(Xs + cc * 64 + t0);
            const float4 w0 = *(const float4*)(Ws + cc * 64 + oc0);
            const float4 w1 = *(const float4*)(Ws + (32 + cc) * 64 + oc0);
            const float4 w2 = *(const float4*)(Ws + (64 + cc) * 64 + oc0);
            const float w0a[4] = {w0.x, w0.y, w0.z, w0.w};
            const float w1a[4] = {w1.x, w1.y, w1.z, w1.w};
            const float w2a[4] = {w2.x, w2.y, w2.z, w2.w};
#pragma unroll
            for (int q = 0; q < 4; q++) {
                const unsigned long long d0 = dup2(w0a[q]);
                const unsigned long long d1 = dup2(w1a[q]);
                const unsigned long long d2 = dup2(w2a[q]);
                a0[q][0] = fma2(d0, xp.x, a0[q][0]); a0[q][1] = fma2(d0, xp.y, a0[q][1]);
                a1[q][0] = fma2(d1, xp.x, a1[q][0]); a1[q][1] = fma2(d1, xp.y, a1[q][1]);
                a2[q][0] = fma2(d2, xp.x, a2[q][0]); a2[q][1] = fma2(d2, xp.y, a2[q][1]);
            }
        }
    }

#pragma unroll
    for (int q = 0; q < 4; q++) {
        const int base = ((b * 64 + oc0 + q) * 512 + n) * 64 + t0;
        float2 lo, hi;
        lo = up2(a0[q][0]); hi = up2(a0[q][1]);
        *(float4*)(z0 + base)   = make_float4(lo.x, lo.y, hi.x, hi.y);
        lo = up2(a1[q][0]); hi = up2(a1[q][1]);
        *(float4*)(g_Z1 + base) = make_float4(lo.x, lo.y, hi.x, hi.y);
        lo = up2(a2[q][0]); hi = up2(a2[q][1]);
        *(float4*)(g_Z2 + base) = make_float4(lo.x, lo.y, hi.x, hi.y);
    }
}

// ---------------- kernel 2: out += norm@Z1 + norm2@Z2  (K = 512) -----------
// block = (i-tile of 128, oc, b). 128 threads, thread = 8 i x 8 t, f32x2 accs.
// norm tiles stored transposed [jj][i] -> LDS.128 reads, conflict-free.
__global__ __launch_bounds__(128, 4) void k_spmm(float* __restrict__ out) {
    __shared__ __align__(16) float Ns [16 * 128];  // [jj][i]
    __shared__ __align__(16) float N2s[16 * 128];
    __shared__ __align__(16) float Z1s[16 * 64];   // [jj][t]
    __shared__ __align__(16) float Z2s[16 * 64];

    const int it = blockIdx.x, oc = blockIdx.y, b = blockIdx.z;
    const int i0g = it * 128;
    const int tid = threadIdx.x;
    const int tx = tid & 7, ty = tid >> 3;
    const int t0 = tx * 8, i0 = ty * 8;
    const int zbase = (b * 64 + oc) * 512 * 64;

    unsigned long long acc[8][4];
#pragma unroll
    for (int r = 0; r < 8; r++)
#pragma unroll
        for (int p = 0; p < 4; p++) acc[r][p] = 0ull;

    for (int j0 = 0; j0 < 512; j0 += 16) {
        __syncthreads();
        // norm / norm2 tiles: 128 i x 16 jj, transposed into smem
#pragma unroll
        for (int itr = 0; itr < 4; itr++) {
            const int idx = itr * 128 + tid;
            const int row = idx >> 2, q = (idx & 3) * 4;
            const float4 v1 = *(const float4*)(g_norm  + (i0g + row) * 512 + j0 + q);
            const float4 v2 = *(const float4*)(g_norm2 + (i0g + row) * 512 + j0 + q);
            Ns [(q + 0) * 128 + row] = v1.x; Ns [(q + 1) * 128 + row] = v1.y;
            Ns [(q + 2) * 128 + row] = v1.z; Ns [(q + 3) * 128 + row] = v1.w;
            N2s[(q + 0) * 128 + row] = v2.x; N2s[(q + 1) * 128 + row] = v2.y;
            N2s[(q + 2) * 128 + row] = v2.z; N2s[(q + 3) * 128 + row] = v2.w;
        }
        // Z tiles: fully contiguous 16 j x 64 t chunk
#pragma unroll
        for (int itr = 0; itr < 2; itr++) {
            const int idx = itr * 128 + tid;
            *(float4*)(Z1s + idx * 4) = *(const float4*)(g_Z1 + zbase + j0 * 64 + idx * 4);
            *(float4*)(Z2s + idx * 4) = *(const float4*)(g_Z2 + zbase + j0 * 64 + idx * 4);
        }
        __syncthreads();

#pragma unroll 4
        for (int jj = 0; jj < 16; jj++) {
            const ulonglong2 z1a = *(const ulonglong2*)(Z1s + jj * 64 + t0);
            const ulonglong2 z1b = *(const ulonglong2*)(Z1s + jj * 64 + t0 + 4);
            const ulonglong2 z2a = *(const ulonglong2*)(Z2s + jj * 64 + t0);
            const ulonglong2 z2b = *(const ulonglong2*)(Z2s + jj * 64 + t0 + 4);
            const unsigned long long z1v[4] = {z1a.x, z1a.y, z1b.x, z1b.y};
            const unsigned long long z2v[4] = {z2a.x, z2a.y, z2b.x, z2b.y};
            const float4 na = *(const float4*)(Ns  + jj * 128 + i0);
            const float4 nb = *(const float4*)(Ns  + jj * 128 + i0 + 4);
            const float4 ma = *(const float4*)(N2s + jj * 128 + i0);
            const float4 mb = *(const float4*)(N2s + jj * 128 + i0 + 4);
            const float nv[8] = {na.x, na.y, na.z, na.w, nb.x, nb.y, nb.z, nb.w};
            const float mv[8] = {ma.x, ma.y, ma.z, ma.w, mb.x, mb.y, mb.z, mb.w};
#pragma unroll
            for (int r = 0; r < 8; r++) {
                const unsigned long long d1 = dup2(nv[r]);
                const unsigned long long d2 = dup2(mv[r]);
#pragma unroll
                for (int p = 0; p < 4; p++) {
                    acc[r][p] = fma2(d1, z1v[p], acc[r][p]);
                    acc[r][p] = fma2(d2, z2v[p], acc[r][p]);
                }
            }
        }
    }

    // epilogue: out (holds Z0 + bias) += spmm result
#pragma unroll
    for (int r = 0; r < 8; r++) {
        const int gbase = zbase + (i0g + i0 + r) * 64 + t0;
#pragma unroll
        for (int v = 0; v < 2; v++) {
            float4 o = *(const float4*)(out + gbase + v * 4);
            const float2 lo = up2(acc[r][v * 2 + 0]);
            const float2 hi = up2(acc[r][v * 2 + 1]);
            o.x += lo.x; o.y += lo.y; o.z += hi.x; o.w += hi.y;
            *(float4*)(out + gbase + v * 4) = o;
        }
    }
}

// ---------------------------------------------------------------------------
extern "C" void kernel_launch(void* const* d_in, const int* in_sizes, int n_in,
                              void* d_out, int out_size) {
    const float* x    = (const float*)d_in[0];   // (16, 64, 512, 64) f32
    const float* adj  = (const float*)d_in[1];   // (512, 512) f32
    const float* W    = (const float*)d_in[2];   // (64, 192) f32
    const float* bias = (const float*)d_in[3];   // (64,) f32
    float* out = (float*)d_out;                  // (16, 64, 512, 64) f32

    k_rownorm<<<N_, 256>>>(adj);
    k_norm2<<<dim3(32, 32), dim3(16, 16)>>>();
    k_mix<<<dim3(N_, B_), 256>>>(x, W, bias, out);
    k_spmm<<<dim3(4, OC_, B_), 128>>>(out);
}

// round 5
// speedup vs baseline: 2.7911x; 2.7911x over previous
#include <cuda_runtime.h>
#include <cstdint>

#define B_  16
#define N_  512
#define T_  64
#define OC_ 64

// ---------------- scratch (device globals; no runtime allocation) ----------
__device__ __align__(16) float g_norm [N_ * N_];
__device__ __align__(16) float g_norm2[N_ * N_];
__device__ __align__(16) float g_Z1[B_ * OC_ * N_ * T_];
__device__ __align__(16) float g_Z2[B_ * OC_ * N_ * T_];
__device__ __align__(16) float g_Wt[192 * 64];      // W transposed: [k][oc]

// ======================= helpers ===========================================
__device__ __forceinline__ uint32_t smem_u32(const void* p) {
    uint32_t a;
    asm("{ .reg .u64 t; cvta.to.shared.u64 t, %1; cvt.u32.u64 %0, t; }"
        : "=r"(a) : "l"(p));
    return a;
}
__device__ __forceinline__ float rtf32(float x) {   // round-to-nearest tf32
    uint32_t r;
    asm("cvt.rn.tf32.f32 %0, %1;" : "=r"(r) : "f"(x));
    return __uint_as_float(r);
}

#define CP16(dst, src) \
    asm volatile("cp.async.cg.shared.global [%0], [%1], 16;" \
                 :: "r"(dst), "l"(src) : "memory")
#define CP_COMMIT()  asm volatile("cp.async.commit_group;" ::: "memory")
#define CP_WAIT1()   asm volatile("cp.async.wait_group 1;" ::: "memory")
#define CP_WAIT0()   asm volatile("cp.async.wait_group 0;" ::: "memory")

#define MMA_TF32(c, a0, a1, a2, a3, b0, b1) \
    asm volatile("mma.sync.aligned.m16n8k8.row.col.f32.tf32.tf32.f32 " \
                 "{%0,%1,%2,%3}, {%4,%5,%6,%7}, {%8,%9}, {%0,%1,%2,%3};" \
                 : "+f"((c)[0]), "+f"((c)[1]), "+f"((c)[2]), "+f"((c)[3]) \
                 : "r"(a0), "r"(a1), "r"(a2), "r"(a3), "r"(b0), "r"(b1))

// ---------------- packed f32x2 helpers (k_mix) ------------------------------
__device__ __forceinline__ unsigned long long dup2(float v) {
    unsigned long long r; asm("mov.b64 %0, {%1, %1};" : "=l"(r) : "f"(v)); return r;
}
__device__ __forceinline__ unsigned long long fma2(unsigned long long a,
                                                   unsigned long long b,
                                                   unsigned long long c) {
    unsigned long long d;
    asm("fma.rn.f32x2 %0, %1, %2, %3;" : "=l"(d) : "l"(a), "l"(b), "l"(c));
    return d;
}
__device__ __forceinline__ float2 up2(unsigned long long p) {
    float2 f; asm("mov.b64 {%0, %1}, %2;" : "=f"(f.x), "=f"(f.y) : "l"(p)); return f;
}

// ---------------- kernel 0a: row-normalized adjacency (tf32-rounded) -------
__global__ void k_rownorm(const float* __restrict__ adj) {
    const int i = blockIdx.x;
    __shared__ float red[256];
    float s = 0.f;
    for (int j = threadIdx.x; j < N_; j += 256) s += adj[i * N_ + j];
    red[threadIdx.x] = s;
    __syncthreads();
    for (int off = 128; off > 0; off >>= 1) {
        if (threadIdx.x < off) red[threadIdx.x] += red[threadIdx.x + off];
        __syncthreads();
    }
    const float inv = 1.0f / (red[0] + 1e-6f);
    for (int j = threadIdx.x; j < N_; j += 256)
        g_norm[i * N_ + j] = rtf32(adj[i * N_ + j] * inv);
}

// ---------------- kernel 0b: norm2 = norm @ norm (tf32-rounded store) ------
__global__ void k_norm2() {
    __shared__ float As[16][16];
    __shared__ float Bs[16][17];
    const int i = blockIdx.y * 16 + threadIdx.y;
    const int j = blockIdx.x * 16 + threadIdx.x;
    float acc = 0.f;
    for (int k0 = 0; k0 < N_; k0 += 16) {
        As[threadIdx.y][threadIdx.x] = g_norm[i * N_ + k0 + threadIdx.x];
        Bs[threadIdx.y][threadIdx.x] = g_norm[(k0 + threadIdx.y) * N_ + j];
        __syncthreads();
#pragma unroll
        for (int k = 0; k < 16; k++) acc += As[threadIdx.y][k] * Bs[k][threadIdx.x];
        __syncthreads();
    }
    g_norm2[i * N_ + j] = rtf32(acc);
}

// ---------------- kernel 0c: transpose W once -------------------------------
__global__ void k_wt(const float* __restrict__ W) {
    const int idx = blockIdx.x * 256 + threadIdx.x;     // idx = k*64 + oc
    if (idx < 192 * 64) {
        const int k = idx >> 6, oc = idx & 63;
        g_Wt[idx] = W[oc * 192 + k];
    }
}

// ---------------- kernel 1: channel mix  Zk = X @ Wk^T ----------------------
// Z0 (+bias, full fp32) -> d_out.  Z1/Z2 tf32-rounded -> scratch.
__global__ __launch_bounds__(256) void k_mix(const float* __restrict__ x,
                                             const float* __restrict__ bias,
                                             float* __restrict__ z0) {
    extern __shared__ float dsm[];
    float* Wts = dsm;              // 12288 floats, [k][oc]
    float* Xs  = dsm + 12288;      // 2048 floats,  [cc][t]
    const int n = blockIdx.x, b = blockIdx.y;
    const int tid = threadIdx.x;
    const int tx = tid & 15, ty = tid >> 4;
    const int t0 = tx * 4, oc0 = ty * 4;

#pragma unroll
    for (int r = 0; r < 12; r++) {
        const int idx = r * 256 + tid;
        *(float4*)(Wts + idx * 4) = *(const float4*)(g_Wt + idx * 4);
    }

    unsigned long long a0[4][2], a1[4][2], a2[4][2];
#pragma unroll
    for (int q = 0; q < 4; q++) {
        const unsigned long long bp = dup2(bias[oc0 + q]);
        a0[q][0] = bp;   a0[q][1] = bp;
        a1[q][0] = 0ull; a1[q][1] = 0ull;
        a2[q][0] = 0ull; a2[q][1] = 0ull;
    }

    for (int h = 0; h < 2; h++) {
        __syncthreads();
        for (int i2 = tid; i2 < 512; i2 += 256) {
            const int cc = i2 >> 4, q = (i2 & 15) * 4;
            *(float4*)(Xs + cc * 64 + q) =
                *(const float4*)(x + ((b * 64 + h * 32 + cc) * 512 + n) * 64 + q);
        }
        __syncthreads();
#pragma unroll 4
        for (int cc = 0; cc < 32; cc++) {
            const ulonglong2 xp = *(const ulonglong2*)(Xs + cc * 64 + t0);
            const int k0 = h * 32 + cc;
            const float4 w0 = *(const float4*)(Wts + k0 * 64 + oc0);
            const float4 w1 = *(const float4*)(Wts + (64 + k0) * 64 + oc0);
            const float4 w2 = *(const float4*)(Wts + (128 + k0) * 64 + oc0);
            const float w0a[4] = {w0.x, w0.y, w0.z, w0.w};
            const float w1a[4] = {w1.x, w1.y, w1.z, w1.w};
            const float w2a[4] = {w2.x, w2.y, w2.z, w2.w};
#pragma unroll
            for (int q = 0; q < 4; q++) {
                const unsigned long long d0 = dup2(w0a[q]);
                const unsigned long long d1 = dup2(w1a[q]);
                const unsigned long long d2 = dup2(w2a[q]);
                a0[q][0] = fma2(d0, xp.x, a0[q][0]); a0[q][1] = fma2(d0, xp.y, a0[q][1]);
                a1[q][0] = fma2(d1, xp.x, a1[q][0]); a1[q][1] = fma2(d1, xp.y, a1[q][1]);
                a2[q][0] = fma2(d2, xp.x, a2[q][0]); a2[q][1] = fma2(d2, xp.y, a2[q][1]);
            }
        }
    }

#pragma unroll
    for (int q = 0; q < 4; q++) {
        const int base = ((b * 64 + oc0 + q) * 512 + n) * 64 + t0;
        float2 lo, hi;
        lo = up2(a0[q][0]); hi = up2(a0[q][1]);
        *(float4*)(z0 + base) = make_float4(lo.x, lo.y, hi.x, hi.y);
        lo = up2(a1[q][0]); hi = up2(a1[q][1]);
        *(float4*)(g_Z1 + base) =
            make_float4(rtf32(lo.x), rtf32(lo.y), rtf32(hi.x), rtf32(hi.y));
        lo = up2(a2[q][0]); hi = up2(a2[q][1]);
        *(float4*)(g_Z2 + base) =
            make_float4(rtf32(lo.x), rtf32(lo.y), rtf32(hi.x), rtf32(hi.y));
    }
}

// ---------------- kernel 2: out += norm@Z1 + norm2@Z2 via mma.sync tf32 -----
// CTA = (i-tile 256, oc-pair, b), 256 thr. Warp: u = wid>>2 (oc), wi = wid&3,
// tile 64i x 64t, m16n8k8 frags. Double-buffered cp.async, K-chunks of 32.
#define AST 36                                    // A smem stride (floats)
#define BST 72                                    // B smem stride (floats)
#define A_BYTES (2 * 256 * AST * 4)               // 73728
#define B_BYTES (4 * 32 * BST * 4)                // 36864
#define STAGE   (A_BYTES + B_BYTES)               // 110592

__global__ __launch_bounds__(256, 1) void k_spmm_mma(float* __restrict__ out) {
    extern __shared__ char sm[];
    const uint32_t sb = smem_u32(sm);
    const int tid = threadIdx.x, wid = tid >> 5, lane = tid & 31;
    const int ih = blockIdx.x, ocp = blockIdx.y, b = blockIdx.z;
    const int i0g = ih * 256, oc0 = ocp * 2;

    const float* zb[4];
    zb[0] = g_Z1 + (b * 64 + oc0) * 32768;
    zb[1] = g_Z2 + (b * 64 + oc0) * 32768;
    zb[2] = g_Z1 + (b * 64 + oc0 + 1) * 32768;
    zb[3] = g_Z2 + (b * 64 + oc0 + 1) * 32768;

    const int u = wid >> 2, wi = wid & 3;
    const int g = lane >> 2, tg = lane & 3;

    float acc[4][8][4];
#pragma unroll
    for (int mt = 0; mt < 4; mt++)
#pragma unroll
        for (int nt = 0; nt < 8; nt++)
#pragma unroll
            for (int r = 0; r < 4; r++) acc[mt][nt][r] = 0.f;

    // ---- stage loader (cp.async, raw copy — data already tf32-exact) ----
    auto load_stage = [&](int c) {
        const int j0 = c * 32;
        const uint32_t st = sb + (uint32_t)(c & 1) * STAGE;
#pragma unroll
        for (int r = 0; r < 16; r++) {                    // A: norm / norm2
            const int idx = r * 256 + tid;
            const int m = idx >> 11, rem = idx & 2047;
            const int row = rem >> 3, q = rem & 7;
            const float* src = (m ? g_norm2 : g_norm) + (i0g + row) * 512 + j0 + q * 4;
            CP16(st + (uint32_t)(m * 36864 + row * (AST * 4) + q * 16), src);
        }
#pragma unroll
        for (int r = 0; r < 8; r++) {                     // B: Z tiles
            const int idx = r * 256 + tid;
            const int tb = idx >> 9, rem = idx & 511;
            const int j = rem >> 4, q = rem & 15;
            const float* src = zb[tb] + (j0 + j) * 64 + q * 4;
            CP16(st + (uint32_t)(A_BYTES + tb * (32 * BST * 4) + j * (BST * 4) + q * 16), src);
        }
        CP_COMMIT();
    };

    load_stage(0);
    for (int c = 0; c < 16; c++) {
        if (c + 1 < 16) { load_stage(c + 1); CP_WAIT1(); }
        else            { CP_WAIT0(); }
        __syncthreads();

        const float* Ab = (const float*)(sm + (size_t)(c & 1) * STAGE);
        const float* Bb = (const float*)(sm + (size_t)(c & 1) * STAGE + A_BYTES);

#pragma unroll
        for (int ks = 0; ks < 4; ks++) {
            uint32_t bf[2][8][2];
#pragma unroll
            for (int m = 0; m < 2; m++) {
                const float* bt = Bb + (u * 2 + m) * (32 * BST);
#pragma unroll
                for (int nt = 0; nt < 8; nt++) {
                    bf[m][nt][0] = __float_as_uint(bt[(ks * 8 + tg) * BST + nt * 8 + g]);
                    bf[m][nt][1] = __float_as_uint(bt[(ks * 8 + tg + 4) * BST + nt * 8 + g]);
                }
            }
#pragma unroll
            for (int mt = 0; mt < 4; mt++) {
#pragma unroll
                for (int m = 0; m < 2; m++) {
                    const float* at = Ab + m * (256 * AST) + (wi * 64 + mt * 16) * AST + ks * 8;
                    const uint32_t a0 = __float_as_uint(at[g * AST + tg]);
                    const uint32_t a1 = __float_as_uint(at[(g + 8) * AST + tg]);
                    const uint32_t a2 = __float_as_uint(at[g * AST + tg + 4]);
                    const uint32_t a3 = __float_as_uint(at[(g + 8) * AST + tg + 4]);
#pragma unroll
                    for (int nt = 0; nt < 8; nt++)
                        MMA_TF32(acc[mt][nt], a0, a1, a2, a3, bf[m][nt][0], bf[m][nt][1]);
                }
            }
        }
        __syncthreads();
    }

    // ---- epilogue: RMW into out (which holds Z0 + bias, fp32-exact) ----
    float* obase = out + (((size_t)(b * 64 + oc0 + u) * 512) + i0g + wi * 64) * 64;
#pragma unroll
    for (int mt = 0; mt < 4; mt++) {
#pragma unroll
        for (int nt = 0; nt < 8; nt++) {
            const int r0 = mt * 16 + g, t0 = nt * 8 + tg * 2;
            float2* p0 = (float2*)(obase + r0 * 64 + t0);
            float2 v0 = *p0;
            v0.x += acc[mt][nt][0]; v0.y += acc[mt][nt][1];
            *p0 = v0;
            float2* p1 = (float2*)(obase + (r0 + 8) * 64 + t0);
            float2 v1 = *p1;
            v1.x += acc[mt][nt][2]; v1.y += acc[mt][nt][3];
            *p1 = v1;
        }
    }
}

// ---------------------------------------------------------------------------
extern "C" void kernel_launch(void* const* d_in, const int* in_sizes, int n_in,
                              void* d_out, int out_size) {
    const float* x    = (const float*)d_in[0];   // (16, 64, 512, 64) f32
    const float* adj  = (const float*)d_in[1];   // (512, 512) f32
    const float* W    = (const float*)d_in[2];   // (64, 192) f32
    const float* bias = (const float*)d_in[3];   // (64,) f32
    float* out = (float*)d_out;                  // (16, 64, 512, 64) f32

    const int mix_smem  = (12288 + 2048) * 4;    // 57344
    const int spmm_smem = 2 * STAGE;             // 221184
    cudaFuncSetAttribute(k_mix, cudaFuncAttributeMaxDynamicSharedMemorySize, mix_smem);
    cudaFuncSetAttribute(k_spmm_mma, cudaFuncAttributeMaxDynamicSharedMemorySize, spmm_smem);

    k_rownorm<<<N_, 256>>>(adj);
    k_norm2<<<dim3(32, 32), dim3(16, 16)>>>();
    k_wt<<<48, 256>>>(W);
    k_mix<<<dim3(N_, B_), 256, mix_smem>>>(x, bias, out);
    k_spmm_mma<<<dim3(2, 32, 16), 256, spmm_smem>>>(out);
}

// round 6
// speedup vs baseline: 3.5400x; 1.2683x over previous
#include <cuda_runtime.h>
#include <cstdint>

#define B_  16
#define N_  512
#define T_  64
#define OC_ 64

// ---------------- scratch (device globals; no runtime allocation) ----------
__device__ __align__(16) float g_norm  [N_ * N_];   // natural (k_norm2 input)
__device__ __align__(16) float g_normp [N_ * N_];   // j8-permuted (spmm A)
__device__ __align__(16) float g_norm2p[N_ * N_];   // j8-permuted (spmm A)
__device__ __align__(16) float g_Z1[B_ * OC_ * N_ * T_];
__device__ __align__(16) float g_Z2[B_ * OC_ * N_ * T_];
__device__ __align__(16) float g_Wt2[64 * 192];     // [c][gc], gc=group*64+oc, tf32-rounded

// j-permutation within 8-blocks: tg and tg+4 become adjacent
__device__ __forceinline__ int jperm(int j) {
    return (j & ~7) | ((j & 3) << 1) | ((j >> 2) & 1);
}

// ======================= helpers ===========================================
__device__ __forceinline__ uint32_t smem_u32(const void* p) {
    uint32_t a;
    asm("{ .reg .u64 t; cvta.to.shared.u64 t, %1; cvt.u32.u64 %0, t; }"
        : "=r"(a) : "l"(p));
    return a;
}
__device__ __forceinline__ float rtf32(float x) {   // round-to-nearest tf32
    uint32_t r;
    asm("cvt.rn.tf32.f32 %0, %1;" : "=r"(r) : "f"(x));
    return __uint_as_float(r);
}
__device__ __forceinline__ uint32_t rtf32u(float x) {
    uint32_t r;
    asm("cvt.rn.tf32.f32 %0, %1;" : "=r"(r) : "f"(x));
    return r;
}

#define CP16(dst, src) \
    asm volatile("cp.async.cg.shared.global [%0], [%1], 16;" \
                 :: "r"(dst), "l"(src) : "memory")
#define CP_COMMIT()  asm volatile("cp.async.commit_group;" ::: "memory")
#define CP_WAIT1()   asm volatile("cp.async.wait_group 1;" ::: "memory")
#define CP_WAIT0()   asm volatile("cp.async.wait_group 0;" ::: "memory")

#define MMA_TF32(c, a0, a1, a2, a3, b0, b1) \
    asm volatile("mma.sync.aligned.m16n8k8.row.col.f32.tf32.tf32.f32 " \
                 "{%0,%1,%2,%3}, {%4,%5,%6,%7}, {%8,%9}, {%0,%1,%2,%3};" \
                 : "+f"((c)[0]), "+f"((c)[1]), "+f"((c)[2]), "+f"((c)[3]) \
                 : "r"(a0), "r"(a1), "r"(a2), "r"(a3), "r"(b0), "r"(b1))

// ---------------- kernel 0a: row-normalized adjacency ----------------------
__global__ void k_rownorm(const float* __restrict__ adj) {
    const int i = blockIdx.x;
    __shared__ float red[256];
    float s = 0.f;
    for (int j = threadIdx.x; j < N_; j += 256) s += adj[i * N_ + j];
    red[threadIdx.x] = s;
    __syncthreads();
    for (int off = 128; off > 0; off >>= 1) {
        if (threadIdx.x < off) red[threadIdx.x] += red[threadIdx.x + off];
        __syncthreads();
    }
    const float inv = 1.0f / (red[0] + 1e-6f);
    for (int j = threadIdx.x; j < N_; j += 256) {
        const float v = rtf32(adj[i * N_ + j] * inv);
        g_norm [i * N_ + j]        = v;
        g_normp[i * N_ + jperm(j)] = v;
    }
}

// ---------------- kernel 0b: norm2 = norm @ norm (permuted store) ----------
__global__ void k_norm2() {
    __shared__ float As[16][16];
    __shared__ float Bs[16][17];
    const int i = blockIdx.y * 16 + threadIdx.y;
    const int j = blockIdx.x * 16 + threadIdx.x;
    float acc = 0.f;
    for (int k0 = 0; k0 < N_; k0 += 16) {
        As[threadIdx.y][threadIdx.x] = g_norm[i * N_ + k0 + threadIdx.x];
        Bs[threadIdx.y][threadIdx.x] = g_norm[(k0 + threadIdx.y) * N_ + j];
        __syncthreads();
#pragma unroll
        for (int k = 0; k < 16; k++) acc += As[threadIdx.y][k] * Bs[k][threadIdx.x];
        __syncthreads();
    }
    g_norm2p[i * N_ + jperm(j)] = rtf32(acc);
}

// ---------------- kernel 0c: W -> [c][gc] layout, tf32-rounded -------------
__global__ void k_wt(const float* __restrict__ W) {
    const int idx = blockIdx.x * 256 + threadIdx.x;     // idx = c*192 + gc
    if (idx < 64 * 192) {
        const int c = idx / 192, gc = idx % 192;
        const int grp = gc >> 6, oc = gc & 63;
        g_Wt2[idx] = rtf32(W[oc * 192 + grp * 64 + c]);
    }
}

// ---------------- kernel 1: channel mix via tensor cores -------------------
// CTA = (n4, cn, b). GEMM: M=256 (4n x 64t), N=96 (half of 192 concat cols),
// K=64 (c). A = X tile (smem [c][m]), B = Wt2 cols (smem [c][gc']).
// Epilogue: transpose via smem -> coalesced 256B stores. Z0+bias -> out,
// Z1/Z2 tf32-rounded -> scratch.
#define XST 264
#define WST 104
#define SST 260
#define MIX_SMEM ((64 * XST + 64 * WST) * 4)   // 94208

__global__ __launch_bounds__(256, 2) void k_mix_tc(const float* __restrict__ x,
                                                   const float* __restrict__ bias,
                                                   float* __restrict__ out) {
    extern __shared__ float dsm[];
    float* Xs = dsm;                 // [c][m], stride 264
    float* Ws = dsm + 64 * XST;      // [c][gc'], stride 104
    const int n0 = blockIdx.x * 4, cn = blockIdx.y, b = blockIdx.z;
    const int tid = threadIdx.x, wid = tid >> 5, lane = tid & 31;
    const int u = wid >> 2, wi = wid & 3;
    const int g = lane >> 2, tg = lane & 3;
    const uint32_t sb = smem_u32(dsm);

    // ---- load X tile (64c x 256m) and W cols (64c x 96) via cp.async ----
#pragma unroll
    for (int r = 0; r < 16; r++) {
        const int i = r * 256 + tid;
        const int c = i >> 6, chunk = i & 63;
        const int nl = chunk >> 4, tq = chunk & 15;
        CP16(sb + (uint32_t)(c * XST + chunk * 4) * 4,
             x + ((b * 64 + c) * 512 + n0 + nl) * 64 + tq * 4);
    }
#pragma unroll
    for (int r = 0; r < 6; r++) {
        const int i = r * 256 + tid;
        const int c = i / 24, q = i % 24;
        CP16(sb + (uint32_t)(64 * XST + c * WST + q * 4) * 4,
             g_Wt2 + c * 192 + cn * 96 + q * 4);
    }
    CP_COMMIT();

    float acc[4][6][4];
#pragma unroll
    for (int mt = 0; mt < 4; mt++)
#pragma unroll
        for (int nt = 0; nt < 6; nt++)
#pragma unroll
            for (int r = 0; r < 4; r++) acc[mt][nt][r] = 0.f;

    CP_WAIT0();
    __syncthreads();

    // ---- mainloop: K=64 = 8 k8-steps ----
#pragma unroll
    for (int ks = 0; ks < 8; ks++) {
        uint32_t bf[6][2];
#pragma unroll
        for (int nt = 0; nt < 6; nt++) {
            bf[nt][0] = __float_as_uint(Ws[(ks * 8 + tg) * WST + u * 48 + nt * 8 + g]);
            bf[nt][1] = __float_as_uint(Ws[(ks * 8 + tg + 4) * WST + u * 48 + nt * 8 + g]);
        }
#pragma unroll
        for (int mt = 0; mt < 4; mt++) {
            const int m0 = wi * 64 + mt * 16;
            const uint32_t a0 = rtf32u(Xs[(ks * 8 + tg) * XST + m0 + g]);
            const uint32_t a1 = rtf32u(Xs[(ks * 8 + tg) * XST + m0 + g + 8]);
            const uint32_t a2 = rtf32u(Xs[(ks * 8 + tg + 4) * XST + m0 + g]);
            const uint32_t a3 = rtf32u(Xs[(ks * 8 + tg + 4) * XST + m0 + g + 8]);
#pragma unroll
            for (int nt = 0; nt < 6; nt++)
                MMA_TF32(acc[mt][nt], a0, a1, a2, a3, bf[nt][0], bf[nt][1]);
        }
    }

    // ---- epilogue: 2 passes through smem transpose Ss[oc'][m] ----
    float* Ss = dsm;                 // reuse (48 x 260 floats = 49920 < 67584)
#pragma unroll
    for (int up = 0; up < 2; up++) {
        __syncthreads();
        if (u == up) {
#pragma unroll
            for (int mt = 0; mt < 4; mt++) {
                const int row = wi * 64 + mt * 16 + g;
#pragma unroll
                for (int nt = 0; nt < 6; nt++) {
                    const int col = nt * 8 + tg * 2;
                    Ss[col * SST + row]           = acc[mt][nt][0];
                    Ss[(col + 1) * SST + row]     = acc[mt][nt][1];
                    Ss[col * SST + row + 8]       = acc[mt][nt][2];
                    Ss[(col + 1) * SST + row + 8] = acc[mt][nt][3];
                }
            }
        }
        __syncthreads();
#pragma unroll
        for (int r = 0; r < 12; r++) {
            const int idx = r * 256 + tid;
            const int ocl = idx >> 6, mq = idx & 63;
            float4 v = *(const float4*)(Ss + ocl * SST + mq * 4);
            const int gc = cn * 96 + up * 48 + ocl;
            const int grp = gc >> 6, oc = gc & 63;
            const int base = ((b * 64 + oc) * 512 + n0 + (mq >> 4)) * 64 + (mq & 15) * 4;
            if (grp == 0) {
                const float bv = __ldg(bias + oc);
                v.x += bv; v.y += bv; v.z += bv; v.w += bv;
                *(float4*)(out + base) = v;
            } else {
                float* dst = (grp == 1) ? g_Z1 : g_Z2;
                *(float4*)(dst + base) =
                    make_float4(rtf32(v.x), rtf32(v.y), rtf32(v.z), rtf32(v.w));
            }
        }
    }
}

// ---------------- kernel 2: out += norm@Z1 + norm2@Z2 (mma tf32) -----------
// CTA = (i-tile 256, oc-pair, b). Kc=16, 3-stage cp.async pipeline, one
// sync/chunk. A (norm, permuted cols) frags via LDS.64; B (Z) scalar LDS.
#define AST 24                                 // A smem stride (floats)
#define BST 72                                 // B smem stride (floats)
#define A_BYTES (2 * 256 * AST * 4)            // 49152
#define B_TILE  (16 * BST * 4)                 // 4608
#define STAGE   (A_BYTES + 4 * B_TILE)         // 67584
#define NCHUNK  32

__global__ __launch_bounds__(256, 1) void k_spmm_mma(float* __restrict__ out) {
    extern __shared__ char sm[];
    const uint32_t sb = smem_u32(sm);
    const int tid = threadIdx.x, wid = tid >> 5, lane = tid & 31;
    const int ih = blockIdx.x, ocp = blockIdx.y, b = blockIdx.z;
    const int i0g = ih * 256, oc0 = ocp * 2;
    const int u = wid >> 2, wi = wid & 3;
    const int g = lane >> 2, tg = lane & 3;

    const float* zb[4];
    zb[0] = g_Z1 + (b * 64 + oc0) * 32768;
    zb[1] = g_Z2 + (b * 64 + oc0) * 32768;
    zb[2] = g_Z1 + (b * 64 + oc0 + 1) * 32768;
    zb[3] = g_Z2 + (b * 64 + oc0 + 1) * 32768;

    float acc[4][8][4];
#pragma unroll
    for (int mt = 0; mt < 4; mt++)
#pragma unroll
        for (int nt = 0; nt < 8; nt++)
#pragma unroll
            for (int r = 0; r < 4; r++) acc[mt][nt][r] = 0.f;

    auto load_stage = [&](int c) {
        const int j0 = c * 16;
        const uint32_t st = sb + (uint32_t)(c % 3) * STAGE;
#pragma unroll
        for (int r = 0; r < 8; r++) {                    // A: 2 x 256 x 16
            const int i = r * 256 + tid;
            const int m = i >> 10, rem = i & 1023;
            const int row = rem >> 2, q = rem & 3;
            CP16(st + (uint32_t)(m * (256 * AST * 4) + row * (AST * 4) + q * 16),
                 (m ? g_norm2p : g_normp) + (i0g + row) * 512 + j0 + q * 4);
        }
#pragma unroll
        for (int r = 0; r < 4; r++) {                    // B: 4 x 16 x 64
            const int i = r * 256 + tid;
            const int tb = i >> 8, rem = i & 255;
            const int j = rem >> 4, q = rem & 15;
            CP16(st + (uint32_t)(A_BYTES + tb * B_TILE + j * (BST * 4) + q * 16),
                 zb[tb] + (j0 + j) * 64 + q * 4);
        }
        CP_COMMIT();
    };

    load_stage(0);
    load_stage(1);

    for (int c = 0; c < NCHUNK; c++) {
        CP_WAIT1();
        __syncthreads();
        if (c + 2 < NCHUNK) load_stage(c + 2);
        else CP_COMMIT();                                 // keep group count uniform

        const float* Ab = (const float*)(sm + (size_t)(c % 3) * STAGE);
        const float* Bb = (const float*)(sm + (size_t)(c % 3) * STAGE + A_BYTES);

#pragma unroll
        for (int ks = 0; ks < 2; ks++) {
            uint32_t bf[2][8][2];
#pragma unroll
            for (int m = 0; m < 2; m++) {
                const float* bt = Bb + (u * 2 + m) * (16 * BST);
#pragma unroll
                for (int nt = 0; nt < 8; nt++) {
                    bf[m][nt][0] = __float_as_uint(bt[(ks * 8 + tg) * BST + nt * 8 + g]);
                    bf[m][nt][1] = __float_as_uint(bt[(ks * 8 + tg + 4) * BST + nt * 8 + g]);
                }
            }
#pragma unroll
            for (int mt = 0; mt < 4; mt++) {
#pragma unroll
                for (int m = 0; m < 2; m++) {
                    const float* at = Ab + m * (256 * AST) + (wi * 64 + mt * 16) * AST;
                    const float2 lo = *(const float2*)(at + g * AST + ks * 8 + 2 * tg);
                    const float2 hi = *(const float2*)(at + (g + 8) * AST + ks * 8 + 2 * tg);
                    const uint32_t a0 = __float_as_uint(lo.x);
                    const uint32_t a2 = __float_as_uint(lo.y);
                    const uint32_t a1 = __float_as_uint(hi.x);
                    const uint32_t a3 = __float_as_uint(hi.y);
#pragma unroll
                    for (int nt = 0; nt < 8; nt++)
                        MMA_TF32(acc[mt][nt], a0, a1, a2, a3, bf[m][nt][0], bf[m][nt][1]);
                }
            }
        }
    }

    // ---- epilogue: RMW into out (holds Z0 + bias) ----
    float* obase = out + (((size_t)(b * 64 + oc0 + u) * 512) + i0g + wi * 64) * 64;
#pragma unroll
    for (int mt = 0; mt < 4; mt++) {
#pragma unroll
        for (int nt = 0; nt < 8; nt++) {
            const int r0 = mt * 16 + g, t0 = nt * 8 + tg * 2;
            float2* p0 = (float2*)(obase + r0 * 64 + t0);
            float2 v0 = *p0;
            v0.x += acc[mt][nt][0]; v0.y += acc[mt][nt][1];
            *p0 = v0;
            float2* p1 = (float2*)(obase + (r0 + 8) * 64 + t0);
            float2 v1 = *p1;
            v1.x += acc[mt][nt][2]; v1.y += acc[mt][nt][3];
            *p1 = v1;
        }
    }
}

// ---------------------------------------------------------------------------
extern "C" void kernel_launch(void* const* d_in, const int* in_sizes, int n_in,
                              void* d_out, int out_size) {
    const float* x    = (const float*)d_in[0];   // (16, 64, 512, 64) f32
    const float* adj  = (const float*)d_in[1];   // (512, 512) f32
    const float* W    = (const float*)d_in[2];   // (64, 192) f32
    const float* bias = (const float*)d_in[3];   // (64,) f32
    float* out = (float*)d_out;                  // (16, 64, 512, 64) f32

    const int spmm_smem = 3 * STAGE;             // 202752
    cudaFuncSetAttribute(k_mix_tc, cudaFuncAttributeMaxDynamicSharedMemorySize, MIX_SMEM);
    cudaFuncSetAttribute(k_spmm_mma, cudaFuncAttributeMaxDynamicSharedMemorySize, spmm_smem);

    k_rownorm<<<N_, 256>>>(adj);
    k_norm2<<<dim3(32, 32), dim3(16, 16)>>>();
    k_wt<<<48, 256>>>(W);
    k_mix_tc<<<dim3(128, 2, 16), 256, MIX_SMEM>>>(x, bias, out);
    k_spmm_mma<<<dim3(2, 32, 16), 256, spmm_smem>>>(out);
}

// round 7
// speedup vs baseline: 5.1652x; 1.4591x over previous
#include <cuda_runtime.h>
#include <cuda_fp16.h>
#include <cstdint>

#define B_  16
#define N_  512
#define T_  64
#define OC_ 64

// ---------------- scratch (device globals; no runtime allocation) ----------
__device__ __align__(16) float  g_norm  [N_ * N_];      // fp32 (k_norm2 input)
__device__ __align__(16) __half g_normh [N_ * N_];      // fp16 (spmm A)
__device__ __align__(16) __half g_norm2h[N_ * N_];      // fp16 (spmm A)
__device__ __align__(16) __half g_Z1h[B_ * OC_ * N_ * T_];
__device__ __align__(16) __half g_Z2h[B_ * OC_ * N_ * T_];
__device__ __align__(16) float  g_Wt2[64 * 192];        // [c][gc], tf32-rounded

// ======================= helpers ===========================================
__device__ __forceinline__ uint32_t smem_u32(const void* p) {
    uint32_t a;
    asm("{ .reg .u64 t; cvta.to.shared.u64 t, %1; cvt.u32.u64 %0, t; }"
        : "=r"(a) : "l"(p));
    return a;
}
__device__ __forceinline__ float rtf32(float x) {
    uint32_t r;
    asm("cvt.rn.tf32.f32 %0, %1;" : "=r"(r) : "f"(x));
    return __uint_as_float(r);
}
__device__ __forceinline__ uint32_t rtf32u(float x) {
    uint32_t r;
    asm("cvt.rn.tf32.f32 %0, %1;" : "=r"(r) : "f"(x));
    return r;
}

#define CP16(dst, src) \
    asm volatile("cp.async.cg.shared.global [%0], [%1], 16;" \
                 :: "r"(dst), "l"(src) : "memory")
#define CP_COMMIT()  asm volatile("cp.async.commit_group;" ::: "memory")
#define CP_WAIT1()   asm volatile("cp.async.wait_group 1;" ::: "memory")
#define CP_WAIT0()   asm volatile("cp.async.wait_group 0;" ::: "memory")

#define MMA_TF32(c, a0, a1, a2, a3, b0, b1) \
    asm volatile("mma.sync.aligned.m16n8k8.row.col.f32.tf32.tf32.f32 " \
                 "{%0,%1,%2,%3}, {%4,%5,%6,%7}, {%8,%9}, {%0,%1,%2,%3};" \
                 : "+f"((c)[0]), "+f"((c)[1]), "+f"((c)[2]), "+f"((c)[3]) \
                 : "r"(a0), "r"(a1), "r"(a2), "r"(a3), "r"(b0), "r"(b1))

#define MMA_F16(c, a0, a1, a2, a3, b0, b1) \
    asm volatile("mma.sync.aligned.m16n8k16.row.col.f32.f16.f16.f32 " \
                 "{%0,%1,%2,%3}, {%4,%5,%6,%7}, {%8,%9}, {%0,%1,%2,%3};" \
                 : "+f"((c)[0]), "+f"((c)[1]), "+f"((c)[2]), "+f"((c)[3]) \
                 : "r"(a0), "r"(a1), "r"(a2), "r"(a3), "r"(b0), "r"(b1))

__device__ __forceinline__ void ldsm_x4(uint32_t* r, uint32_t addr) {
    asm volatile("ldmatrix.sync.aligned.m8n8.x4.shared.b16 {%0,%1,%2,%3}, [%4];"
                 : "=r"(r[0]), "=r"(r[1]), "=r"(r[2]), "=r"(r[3]) : "r"(addr));
}
__device__ __forceinline__ void ldsm_x4t(uint32_t* r, uint32_t addr) {
    asm volatile("ldmatrix.sync.aligned.m8n8.x4.trans.shared.b16 {%0,%1,%2,%3}, [%4];"
                 : "=r"(r[0]), "=r"(r[1]), "=r"(r[2]), "=r"(r[3]) : "r"(addr));
}

// ---------------- kernel 0a: row-normalized adjacency ----------------------
__global__ void k_rownorm(const float* __restrict__ adj) {
    const int i = blockIdx.x;
    __shared__ float red[256];
    float s = 0.f;
    for (int j = threadIdx.x; j < N_; j += 256) s += adj[i * N_ + j];
    red[threadIdx.x] = s;
    __syncthreads();
    for (int off = 128; off > 0; off >>= 1) {
        if (threadIdx.x < off) red[threadIdx.x] += red[threadIdx.x + off];
        __syncthreads();
    }
    const float inv = 1.0f / (red[0] + 1e-6f);
    for (int j = threadIdx.x; j < N_; j += 256) {
        const float v = adj[i * N_ + j] * inv;
        g_norm [i * N_ + j] = v;
        g_normh[i * N_ + j] = __float2half_rn(v);
    }
}

// ---------------- kernel 0b: norm2 = norm @ norm (fp16 store) --------------
__global__ void k_norm2() {
    __shared__ float As[16][16];
    __shared__ float Bs[16][17];
    const int i = blockIdx.y * 16 + threadIdx.y;
    const int j = blockIdx.x * 16 + threadIdx.x;
    float acc = 0.f;
    for (int k0 = 0; k0 < N_; k0 += 16) {
        As[threadIdx.y][threadIdx.x] = g_norm[i * N_ + k0 + threadIdx.x];
        Bs[threadIdx.y][threadIdx.x] = g_norm[(k0 + threadIdx.y) * N_ + j];
        __syncthreads();
#pragma unroll
        for (int k = 0; k < 16; k++) acc += As[threadIdx.y][k] * Bs[k][threadIdx.x];
        __syncthreads();
    }
    g_norm2h[i * N_ + j] = __float2half_rn(acc);
}

// ---------------- kernel 0c: W -> [c][gc] layout, tf32-rounded -------------
__global__ void k_wt(const float* __restrict__ W) {
    const int idx = blockIdx.x * 256 + threadIdx.x;     // idx = c*192 + gc
    if (idx < 64 * 192) {
        const int c = idx / 192, gc = idx % 192;
        const int grp = gc >> 6, oc = gc & 63;
        g_Wt2[idx] = rtf32(W[oc * 192 + grp * 64 + c]);
    }
}

// ---------------- kernel 1: channel mix via tensor cores (tf32) ------------
// CTA = (n4, cn, b). GEMM: M=256 (4n x 64t), N=96, K=64.
// Z0+bias (fp32) -> out; Z1/Z2 (fp16 RN) -> scratch.
#define XST 264
#define WST 104
#define SST 260
#define MIX_SMEM ((64 * XST + 64 * WST) * 4)   // 94208

__global__ __launch_bounds__(256, 2) void k_mix_tc(const float* __restrict__ x,
                                                   const float* __restrict__ bias,
                                                   float* __restrict__ out) {
    extern __shared__ float dsm[];
    float* Xs = dsm;                 // [c][m], stride 264
    float* Ws = dsm + 64 * XST;      // [c][gc'], stride 104
    const int n0 = blockIdx.x * 4, cn = blockIdx.y, b = blockIdx.z;
    const int tid = threadIdx.x, wid = tid >> 5, lane = tid & 31;
    const int u = wid >> 2, wi = wid & 3;
    const int g = lane >> 2, tg = lane & 3;
    const uint32_t sb = smem_u32(dsm);

#pragma unroll
    for (int r = 0; r < 16; r++) {
        const int i = r * 256 + tid;
        const int c = i >> 6, chunk = i & 63;
        const int nl = chunk >> 4, tq = chunk & 15;
        CP16(sb + (uint32_t)(c * XST + chunk * 4) * 4,
             x + ((b * 64 + c) * 512 + n0 + nl) * 64 + tq * 4);
    }
#pragma unroll
    for (int r = 0; r < 6; r++) {
        const int i = r * 256 + tid;
        const int c = i / 24, q = i % 24;
        CP16(sb + (uint32_t)(64 * XST + c * WST + q * 4) * 4,
             g_Wt2 + c * 192 + cn * 96 + q * 4);
    }
    CP_COMMIT();

    float acc[4][6][4];
#pragma unroll
    for (int mt = 0; mt < 4; mt++)
#pragma unroll
        for (int nt = 0; nt < 6; nt++)
#pragma unroll
            for (int r = 0; r < 4; r++) acc[mt][nt][r] = 0.f;

    CP_WAIT0();
    __syncthreads();

#pragma unroll
    for (int ks = 0; ks < 8; ks++) {
        uint32_t bf[6][2];
#pragma unroll
        for (int nt = 0; nt < 6; nt++) {
            bf[nt][0] = __float_as_uint(Ws[(ks * 8 + tg) * WST + u * 48 + nt * 8 + g]);
            bf[nt][1] = __float_as_uint(Ws[(ks * 8 + tg + 4) * WST + u * 48 + nt * 8 + g]);
        }
#pragma unroll
        for (int mt = 0; mt < 4; mt++) {
            const int m0 = wi * 64 + mt * 16;
            const uint32_t a0 = rtf32u(Xs[(ks * 8 + tg) * XST + m0 + g]);
            const uint32_t a1 = rtf32u(Xs[(ks * 8 + tg) * XST + m0 + g + 8]);
            const uint32_t a2 = rtf32u(Xs[(ks * 8 + tg + 4) * XST + m0 + g]);
            const uint32_t a3 = rtf32u(Xs[(ks * 8 + tg + 4) * XST + m0 + g + 8]);
#pragma unroll
            for (int nt = 0; nt < 6; nt++)
                MMA_TF32(acc[mt][nt], a0, a1, a2, a3, bf[nt][0], bf[nt][1]);
        }
    }

    // ---- epilogue: 2 passes through smem transpose Ss[oc'][m] ----
    float* Ss = dsm;
#pragma unroll
    for (int up = 0; up < 2; up++) {
        __syncthreads();
        if (u == up) {
#pragma unroll
            for (int mt = 0; mt < 4; mt++) {
                const int row = wi * 64 + mt * 16 + g;
#pragma unroll
                for (int nt = 0; nt < 6; nt++) {
                    const int col = nt * 8 + tg * 2;
                    Ss[col * SST + row]           = acc[mt][nt][0];
                    Ss[(col + 1) * SST + row]     = acc[mt][nt][1];
                    Ss[col * SST + row + 8]       = acc[mt][nt][2];
                    Ss[(col + 1) * SST + row + 8] = acc[mt][nt][3];
                }
            }
        }
        __syncthreads();
#pragma unroll
        for (int r = 0; r < 12; r++) {
            const int idx = r * 256 + tid;
            const int ocl = idx >> 6, mq = idx & 63;
            float4 v = *(const float4*)(Ss + ocl * SST + mq * 4);
            const int gc = cn * 96 + up * 48 + ocl;
            const int grp = gc >> 6, oc = gc & 63;
            const int base = ((b * 64 + oc) * 512 + n0 + (mq >> 4)) * 64 + (mq & 15) * 4;
            if (grp == 0) {
                const float bv = __ldg(bias + oc);
                v.x += bv; v.y += bv; v.z += bv; v.w += bv;
                *(float4*)(out + base) = v;
            } else {
                __half* dst = (grp == 1) ? g_Z1h : g_Z2h;
                union { __half2 h[2]; uint2 u2; } cv;
                cv.h[0] = __floats2half2_rn(v.x, v.y);
                cv.h[1] = __floats2half2_rn(v.z, v.w);
                *(uint2*)(dst + base) = cv.u2;
            }
        }
    }
}

// ---------------- kernel 2: out += norm@Z1 + norm2@Z2 (fp16 mma) -----------
// CTA = (i-tile 256, oc-pair, b). Kc=32, 3-stage cp.async, ldmatrix frags.
// A stride 80B, B stride 144B -> conflict-free ldmatrix wavefronts.
#define AHST 40                                // A smem stride (halves) = 80B
#define BHST 72                                // B smem stride (halves) = 144B
#define A_BYTES (2 * 256 * AHST * 2)           // 40960
#define B_TILE  (32 * BHST * 2)                // 4608
#define STAGE   (A_BYTES + 4 * B_TILE)         // 59392
#define NCHUNK  16

__global__ __launch_bounds__(256, 1) void k_spmm_mma(float* __restrict__ out) {
    extern __shared__ char sm[];
    const uint32_t sb = smem_u32(sm);
    const int tid = threadIdx.x, wid = tid >> 5, lane = tid & 31;
    const int ih = blockIdx.x, ocp = blockIdx.y, b = blockIdx.z;
    const int i0g = ih * 256, oc0 = ocp * 2;
    const int u = wid >> 2, wi = wid & 3;
    const int g = lane >> 2, tg = lane & 3;
    const int q = lane >> 3, rr = lane & 7;    // ldmatrix quadrant / row

    const __half* zb[4];
    zb[0] = g_Z1h + (size_t)(b * 64 + oc0) * 32768;
    zb[1] = g_Z2h + (size_t)(b * 64 + oc0) * 32768;
    zb[2] = g_Z1h + (size_t)(b * 64 + oc0 + 1) * 32768;
    zb[3] = g_Z2h + (size_t)(b * 64 + oc0 + 1) * 32768;

    float acc[4][8][4];
#pragma unroll
    for (int mt = 0; mt < 4; mt++)
#pragma unroll
        for (int nt = 0; nt < 8; nt++)
#pragma unroll
            for (int r = 0; r < 4; r++) acc[mt][nt][r] = 0.f;

    auto load_stage = [&](int c) {
        const int j0 = c * 32;
        const uint32_t st = sb + (uint32_t)(c % 3) * STAGE;
#pragma unroll
        for (int r = 0; r < 8; r++) {                    // A: 2 x 256 x 32h
            const int i = r * 256 + tid;
            const int m = i >> 10, rem = i & 1023;
            const int row = rem >> 2, qq = rem & 3;
            CP16(st + (uint32_t)(m * (256 * AHST * 2) + row * (AHST * 2) + qq * 16),
                 (m ? g_norm2h : g_normh) + (i0g + row) * 512 + j0 + qq * 8);
        }
#pragma unroll
        for (int r = 0; r < 4; r++) {                    // B: 4 x 32 x 64h
            const int i = r * 256 + tid;
            const int tb = i >> 8, rem = i & 255;
            const int j = rem >> 3, qq = rem & 7;
            CP16(st + (uint32_t)(A_BYTES + tb * B_TILE + j * (BHST * 2) + qq * 16),
                 zb[tb] + (j0 + j) * 64 + qq * 8);
        }
        CP_COMMIT();
    };

    load_stage(0);
    load_stage(1);

    for (int c = 0; c < NCHUNK; c++) {
        CP_WAIT1();
        __syncthreads();
        if (c + 2 < NCHUNK) load_stage(c + 2);
        else CP_COMMIT();                                 // uniform group count

        const uint32_t aA = sb + (uint32_t)(c % 3) * STAGE;
        const uint32_t aB = aA + A_BYTES;

#pragma unroll
        for (int ks = 0; ks < 2; ks++) {
            uint32_t bf[2][4][4];
#pragma unroll
            for (int m = 0; m < 2; m++) {
#pragma unroll
                for (int ntp = 0; ntp < 4; ntp++) {
                    const int rowB = ks * 16 + (q & 1) * 8 + rr;
                    const int colB = ntp * 16 + (q >> 1) * 8;
                    ldsm_x4t(bf[m][ntp],
                             aB + (uint32_t)((u * 2 + m) * 32 * BHST + rowB * BHST + colB) * 2);
                }
            }
#pragma unroll
            for (int mt = 0; mt < 4; mt++) {
#pragma unroll
                for (int m = 0; m < 2; m++) {
                    const int rowA = wi * 64 + mt * 16 + (q & 1) * 8 + rr;
                    const int colA = ks * 16 + (q >> 1) * 8;
                    uint32_t af[4];
                    ldsm_x4(af, aA + (uint32_t)(m * 256 * AHST + rowA * AHST + colA) * 2);
#pragma unroll
                    for (int nt = 0; nt < 8; nt++)
                        MMA_F16(acc[mt][nt], af[0], af[1], af[2], af[3],
                                bf[m][nt >> 1][(nt & 1) * 2],
                                bf[m][nt >> 1][(nt & 1) * 2 + 1]);
                }
            }
        }
    }

    // ---- epilogue: RMW into out (holds Z0 + bias, fp32) ----
    float* obase = out + (((size_t)(b * 64 + oc0 + u) * 512) + i0g + wi * 64) * 64;
#pragma unroll
    for (int mt = 0; mt < 4; mt++) {
#pragma unroll
        for (int nt = 0; nt < 8; nt++) {
            const int r0 = mt * 16 + g, t0 = nt * 8 + tg * 2;
            float2* p0 = (float2*)(obase + r0 * 64 + t0);
            float2 v0 = *p0;
            v0.x += acc[mt][nt][0]; v0.y += acc[mt][nt][1];
            *p0 = v0;
            float2* p1 = (float2*)(obase + (r0 + 8) * 64 + t0);
            float2 v1 = *p1;
            v1.x += acc[mt][nt][2]; v1.y += acc[mt][nt][3];
            *p1 = v1;
        }
    }
}

// ---------------------------------------------------------------------------
extern "C" void kernel_launch(void* const* d_in, const int* in_sizes, int n_in,
                              void* d_out, int out_size) {
    const float* x    = (const float*)d_in[0];   // (16, 64, 512, 64) f32
    const float* adj  = (const float*)d_in[1];   // (512, 512) f32
    const float* W    = (const float*)d_in[2];   // (64, 192) f32
    const float* bias = (const float*)d_in[3];   // (64,) f32
    float* out = (float*)d_out;                  // (16, 64, 512, 64) f32

    const int spmm_smem = 3 * STAGE;             // 178176
    cudaFuncSetAttribute(k_mix_tc, cudaFuncAttributeMaxDynamicSharedMemorySize, MIX_SMEM);
    cudaFuncSetAttribute(k_spmm_mma, cudaFuncAttributeMaxDynamicSharedMemorySize, spmm_smem);

    k_rownorm<<<N_, 256>>>(adj);
    k_norm2<<<dim3(32, 32), dim3(16, 16)>>>();
    k_wt<<<48, 256>>>(W);
    k_mix_tc<<<dim3(128, 2, 16), 256, MIX_SMEM>>>(x, bias, out);
    k_spmm_mma<<<dim3(2, 32, 16), 256, spmm_smem>>>(out);
}

// round 8
// speedup vs baseline: 5.1719x; 1.0013x over previous
#include <cuda_runtime.h>
#include <cuda_fp16.h>
#include <cstdint>

#define B_  16
#define N_  512
#define T_  64
#define OC_ 64

// ---------------- scratch (device globals; no runtime allocation) ----------
__device__ __align__(16) float  g_norm  [N_ * N_];      // fp32 (k_norm2 input)
__device__ __align__(16) __half g_normh [N_ * N_];      // fp16 (spmm A)
__device__ __align__(16) __half g_norm2h[N_ * N_];      // fp16 (spmm A)
__device__ __align__(16) __half g_Z1h[B_ * OC_ * N_ * T_];
__device__ __align__(16) __half g_Z2h[B_ * OC_ * N_ * T_];
__device__ __align__(16) float  g_Wt2[64 * 192];        // [c][gc], tf32-rounded

// ======================= helpers ===========================================
__device__ __forceinline__ uint32_t smem_u32(const void* p) {
    uint32_t a;
    asm("{ .reg .u64 t; cvta.to.shared.u64 t, %1; cvt.u32.u64 %0, t; }"
        : "=r"(a) : "l"(p));
    return a;
}
__device__ __forceinline__ float rtf32(float x) {
    uint32_t r;
    asm("cvt.rn.tf32.f32 %0, %1;" : "=r"(r) : "f"(x));
    return __uint_as_float(r);
}
__device__ __forceinline__ uint32_t rtf32u(float x) {
    uint32_t r;
    asm("cvt.rn.tf32.f32 %0, %1;" : "=r"(r) : "f"(x));
    return r;
}

#define CP16(dst, src) \
    asm volatile("cp.async.cg.shared.global [%0], [%1], 16;" \
                 :: "r"(dst), "l"(src) : "memory")
#define CP_COMMIT()  asm volatile("cp.async.commit_group;" ::: "memory")
#define CP_WAIT1()   asm volatile("cp.async.wait_group 1;" ::: "memory")
#define CP_WAIT0()   asm volatile("cp.async.wait_group 0;" ::: "memory")

#define MMA_TF32(c, a0, a1, a2, a3, b0, b1) \
    asm volatile("mma.sync.aligned.m16n8k8.row.col.f32.tf32.tf32.f32 " \
                 "{%0,%1,%2,%3}, {%4,%5,%6,%7}, {%8,%9}, {%0,%1,%2,%3};" \
                 : "+f"((c)[0]), "+f"((c)[1]), "+f"((c)[2]), "+f"((c)[3]) \
                 : "r"(a0), "r"(a1), "r"(a2), "r"(a3), "r"(b0), "r"(b1))

#define MMA_F16(c, a0, a1, a2, a3, b0, b1) \
    asm volatile("mma.sync.aligned.m16n8k16.row.col.f32.f16.f16.f32 " \
                 "{%0,%1,%2,%3}, {%4,%5,%6,%7}, {%8,%9}, {%0,%1,%2,%3};" \
                 : "+f"((c)[0]), "+f"((c)[1]), "+f"((c)[2]), "+f"((c)[3]) \
                 : "r"(a0), "r"(a1), "r"(a2), "r"(a3), "r"(b0), "r"(b1))

__device__ __forceinline__ void ldsm_x4(uint32_t* r, uint32_t addr) {
    asm volatile("ldmatrix.sync.aligned.m8n8.x4.shared.b16 {%0,%1,%2,%3}, [%4];"
                 : "=r"(r[0]), "=r"(r[1]), "=r"(r[2]), "=r"(r[3]) : "r"(addr));
}
__device__ __forceinline__ void ldsm_x4t(uint32_t* r, uint32_t addr) {
    asm volatile("ldmatrix.sync.aligned.m8n8.x4.trans.shared.b16 {%0,%1,%2,%3}, [%4];"
                 : "=r"(r[0]), "=r"(r[1]), "=r"(r[2]), "=r"(r[3]) : "r"(addr));
}

// ---------------- kernel 0a: row-normalized adjacency ----------------------
__global__ void k_rownorm(const float* __restrict__ adj) {
    const int i = blockIdx.x;
    __shared__ float red[256];
    float s = 0.f;
    for (int j = threadIdx.x; j < N_; j += 256) s += adj[i * N_ + j];
    red[threadIdx.x] = s;
    __syncthreads();
    for (int off = 128; off > 0; off >>= 1) {
        if (threadIdx.x < off) red[threadIdx.x] += red[threadIdx.x + off];
        __syncthreads();
    }
    const float inv = 1.0f / (red[0] + 1e-6f);
    for (int j = threadIdx.x; j < N_; j += 256) {
        const float v = adj[i * N_ + j] * inv;
        g_norm [i * N_ + j] = v;
        g_normh[i * N_ + j] = __float2half_rn(v);
    }
}

// ---------------- kernel 0b: norm2 = norm @ norm (fp16 store) --------------
__global__ void k_norm2() {
    __shared__ float As[16][16];
    __shared__ float Bs[16][17];
    const int i = blockIdx.y * 16 + threadIdx.y;
    const int j = blockIdx.x * 16 + threadIdx.x;
    float acc = 0.f;
    for (int k0 = 0; k0 < N_; k0 += 16) {
        As[threadIdx.y][threadIdx.x] = g_norm[i * N_ + k0 + threadIdx.x];
        Bs[threadIdx.y][threadIdx.x] = g_norm[(k0 + threadIdx.y) * N_ + j];
        __syncthreads();
#pragma unroll
        for (int k = 0; k < 16; k++) acc += As[threadIdx.y][k] * Bs[k][threadIdx.x];
        __syncthreads();
    }
    g_norm2h[i * N_ + j] = __float2half_rn(acc);
}

// ---------------- kernel 0c: W -> [c][gc] layout, tf32-rounded -------------
__global__ void k_wt(const float* __restrict__ W) {
    const int idx = blockIdx.x * 256 + threadIdx.x;     // idx = c*192 + gc
    if (idx < 64 * 192) {
        const int c = idx / 192, gc = idx % 192;
        const int grp = gc >> 6, oc = gc & 63;
        g_Wt2[idx] = rtf32(W[oc * 192 + grp * 64 + c]);
    }
}

// ---------------- kernel 1: channel mix via tensor cores (tf32) ------------
// CTA = (n4, cn, b). GEMM: M=256 (4n x 64t), N=96, K=64.
// Z0+bias (fp32) -> out; Z1/Z2 (fp16 RN) -> scratch.
#define XST 264
#define WST 104
#define SST 260
#define MIX_SMEM ((64 * XST + 64 * WST) * 4)   // 94208

__global__ __launch_bounds__(256, 2) void k_mix_tc(const float* __restrict__ x,
                                                   const float* __restrict__ bias,
                                                   float* __restrict__ out) {
    extern __shared__ float dsm[];
    float* Xs = dsm;                 // [c][m], stride 264
    float* Ws = dsm + 64 * XST;      // [c][gc'], stride 104
    const int n0 = blockIdx.x * 4, cn = blockIdx.y, b = blockIdx.z;
    const int tid = threadIdx.x, wid = tid >> 5, lane = tid & 31;
    const int u = wid >> 2, wi = wid & 3;
    const int g = lane >> 2, tg = lane & 3;
    const uint32_t sb = smem_u32(dsm);

#pragma unroll
    for (int r = 0; r < 16; r++) {
        const int i = r * 256 + tid;
        const int c = i >> 6, chunk = i & 63;
        const int nl = chunk >> 4, tq = chunk & 15;
        CP16(sb + (uint32_t)(c * XST + chunk * 4) * 4,
             x + ((b * 64 + c) * 512 + n0 + nl) * 64 + tq * 4);
    }
#pragma unroll
    for (int r = 0; r < 6; r++) {
        const int i = r * 256 + tid;
        const int c = i / 24, q = i % 24;
        CP16(sb + (uint32_t)(64 * XST + c * WST + q * 4) * 4,
             g_Wt2 + c * 192 + cn * 96 + q * 4);
    }
    CP_COMMIT();

    float acc[4][6][4];
#pragma unroll
    for (int mt = 0; mt < 4; mt++)
#pragma unroll
        for (int nt = 0; nt < 6; nt++)
#pragma unroll
            for (int r = 0; r < 4; r++) acc[mt][nt][r] = 0.f;

    CP_WAIT0();
    __syncthreads();

#pragma unroll
    for (int ks = 0; ks < 8; ks++) {
        uint32_t bf[6][2];
#pragma unroll
        for (int nt = 0; nt < 6; nt++) {
            bf[nt][0] = __float_as_uint(Ws[(ks * 8 + tg) * WST + u * 48 + nt * 8 + g]);
            bf[nt][1] = __float_as_uint(Ws[(ks * 8 + tg + 4) * WST + u * 48 + nt * 8 + g]);
        }
#pragma unroll
        for (int mt = 0; mt < 4; mt++) {
            const int m0 = wi * 64 + mt * 16;
            const uint32_t a0 = rtf32u(Xs[(ks * 8 + tg) * XST + m0 + g]);
            const uint32_t a1 = rtf32u(Xs[(ks * 8 + tg) * XST + m0 + g + 8]);
            const uint32_t a2 = rtf32u(Xs[(ks * 8 + tg + 4) * XST + m0 + g]);
            const uint32_t a3 = rtf32u(Xs[(ks * 8 + tg + 4) * XST + m0 + g + 8]);
#pragma unroll
            for (int nt = 0; nt < 6; nt++)
                MMA_TF32(acc[mt][nt], a0, a1, a2, a3, bf[nt][0], bf[nt][1]);
        }
    }

    // ---- epilogue: 2 passes through smem transpose Ss[oc'][m] ----
    float* Ss = dsm;
#pragma unroll
    for (int up = 0; up < 2; up++) {
        __syncthreads();
        if (u == up) {
#pragma unroll
            for (int mt = 0; mt < 4; mt++) {
                const int row = wi * 64 + mt * 16 + g;
#pragma unroll
                for (int nt = 0; nt < 6; nt++) {
                    const int col = nt * 8 + tg * 2;
                    Ss[col * SST + row]           = acc[mt][nt][0];
                    Ss[(col + 1) * SST + row]     = acc[mt][nt][1];
                    Ss[col * SST + row + 8]       = acc[mt][nt][2];
                    Ss[(col + 1) * SST + row + 8] = acc[mt][nt][3];
                }
            }
        }
        __syncthreads();
#pragma unroll
        for (int r = 0; r < 12; r++) {
            const int idx = r * 256 + tid;
            const int ocl = idx >> 6, mq = idx & 63;
            float4 v = *(const float4*)(Ss + ocl * SST + mq * 4);
            const int gc = cn * 96 + up * 48 + ocl;
            const int grp = gc >> 6, oc = gc & 63;
            const int base = ((b * 64 + oc) * 512 + n0 + (mq >> 4)) * 64 + (mq & 15) * 4;
            if (grp == 0) {
                const float bv = __ldg(bias + oc);
                v.x += bv; v.y += bv; v.z += bv; v.w += bv;
                *(float4*)(out + base) = v;
            } else {
                __half* dst = (grp == 1) ? g_Z1h : g_Z2h;
                union { __half2 h[2]; uint2 u2; } cv;
                cv.h[0] = __floats2half2_rn(v.x, v.y);
                cv.h[1] = __floats2half2_rn(v.z, v.w);
                *(uint2*)(dst + base) = cv.u2;
            }
        }
    }
}

// ---------------- kernel 2: out += norm@Z1 + norm2@Z2 (fp16 mma) -----------
// CTA = (i-tile 256, oc-pair, b), 512 threads / 16 warps (4 per SMSP).
// Warp = (wi: 64i block) x (u: ocl = u>>1, t-half th = u&1) -> 64i x 32t.
// Kc=32, 3-stage cp.async, ldmatrix frags; A stride 80B, B stride 144B.
#define AHST 40                                // A smem stride (halves) = 80B
#define BHST 72                                // B smem stride (halves) = 144B
#define A_BYTES (2 * 256 * AHST * 2)           // 40960
#define B_TILE  (32 * BHST * 2)                // 4608
#define STAGE   (A_BYTES + 4 * B_TILE)         // 59392
#define NCHUNK  16

__global__ __launch_bounds__(512, 1) void k_spmm_mma(float* __restrict__ out) {
    extern __shared__ char sm[];
    const uint32_t sb = smem_u32(sm);
    const int tid = threadIdx.x, wid = tid >> 5, lane = tid & 31;
    const int ih = blockIdx.x, ocp = blockIdx.y, b = blockIdx.z;
    const int i0g = ih * 256, oc0 = ocp * 2;
    const int u = wid >> 2, wi = wid & 3;
    const int ocl = u >> 1, th = u & 1;        // oc within pair / t-half
    const int g = lane >> 2, tg = lane & 3;
    const int q = lane >> 3, rr = lane & 7;    // ldmatrix quadrant / row

    const __half* zb[4];
    zb[0] = g_Z1h + (size_t)(b * 64 + oc0) * 32768;
    zb[1] = g_Z2h + (size_t)(b * 64 + oc0) * 32768;
    zb[2] = g_Z1h + (size_t)(b * 64 + oc0 + 1) * 32768;
    zb[3] = g_Z2h + (size_t)(b * 64 + oc0 + 1) * 32768;

    float acc[4][4][4];
#pragma unroll
    for (int mt = 0; mt < 4; mt++)
#pragma unroll
        for (int nt = 0; nt < 4; nt++)
#pragma unroll
            for (int r = 0; r < 4; r++) acc[mt][nt][r] = 0.f;

    auto load_stage = [&](int c) {
        const int j0 = c * 32;
        const uint32_t st = sb + (uint32_t)(c % 3) * STAGE;
#pragma unroll
        for (int r = 0; r < 4; r++) {                    // A: 2 x 256 x 32h
            const int i = r * 512 + tid;
            const int m = i >> 10, rem = i & 1023;
            const int row = rem >> 2, qq = rem & 3;
            CP16(st + (uint32_t)(m * (256 * AHST * 2) + row * (AHST * 2) + qq * 16),
                 (m ? g_norm2h : g_normh) + (i0g + row) * 512 + j0 + qq * 8);
        }
#pragma unroll
        for (int r = 0; r < 2; r++) {                    // B: 4 x 32 x 64h
            const int i = r * 512 + tid;
            const int tb = i >> 8, rem = i & 255;
            const int j = rem >> 3, qq = rem & 7;
            CP16(st + (uint32_t)(A_BYTES + tb * B_TILE + j * (BHST * 2) + qq * 16),
                 zb[tb] + (j0 + j) * 64 + qq * 8);
        }
        CP_COMMIT();
    };

    load_stage(0);
    load_stage(1);

    for (int c = 0; c < NCHUNK; c++) {
        CP_WAIT1();
        __syncthreads();
        if (c + 2 < NCHUNK) load_stage(c + 2);
        else CP_COMMIT();                                 // uniform group count

        const uint32_t aA = sb + (uint32_t)(c % 3) * STAGE;
        const uint32_t aB = aA + A_BYTES;

#pragma unroll
        for (int ks = 0; ks < 2; ks++) {
            uint32_t bf[2][2][4];
#pragma unroll
            for (int m = 0; m < 2; m++) {
#pragma unroll
                for (int ntp = 0; ntp < 2; ntp++) {
                    const int rowB = ks * 16 + (q & 1) * 8 + rr;
                    const int colB = th * 32 + ntp * 16 + (q >> 1) * 8;
                    ldsm_x4t(bf[m][ntp],
                             aB + (uint32_t)((ocl * 2 + m) * 32 * BHST + rowB * BHST + colB) * 2);
                }
            }
#pragma unroll
            for (int mt = 0; mt < 4; mt++) {
#pragma unroll
                for (int m = 0; m < 2; m++) {
                    const int rowA = wi * 64 + mt * 16 + (q & 1) * 8 + rr;
                    const int colA = ks * 16 + (q >> 1) * 8;
                    uint32_t af[4];
                    ldsm_x4(af, aA + (uint32_t)(m * 256 * AHST + rowA * AHST + colA) * 2);
#pragma unroll
                    for (int nt = 0; nt < 4; nt++)
                        MMA_F16(acc[mt][nt], af[0], af[1], af[2], af[3],
                                bf[m][nt >> 1][(nt & 1) * 2],
                                bf[m][nt >> 1][(nt & 1) * 2 + 1]);
                }
            }
        }
    }

    // ---- epilogue: RMW into out (holds Z0 + bias, fp32) ----
    float* obase = out + (((size_t)(b * 64 + oc0 + ocl) * 512) + i0g + wi * 64) * 64;
#pragma unroll
    for (int mt = 0; mt < 4; mt++) {
#pragma unroll
        for (int nt = 0; nt < 4; nt++) {
            const int r0 = mt * 16 + g, t0 = th * 32 + nt * 8 + tg * 2;
            float2* p0 = (float2*)(obase + r0 * 64 + t0);
            float2 v0 = *p0;
            v0.x += acc[mt][nt][0]; v0.y += acc[mt][nt][1];
            *p0 = v0;
            float2* p1 = (float2*)(obase + (r0 + 8) * 64 + t0);
            float2 v1 = *p1;
            v1.x += acc[mt][nt][2]; v1.y += acc[mt][nt][3];
            *p1 = v1;
        }
    }
}

// ---------------------------------------------------------------------------
extern "C" void kernel_launch(void* const* d_in, const int* in_sizes, int n_in,
                              void* d_out, int out_size) {
    const float* x    = (const float*)d_in[0];   // (16, 64, 512, 64) f32
    const float* adj  = (const float*)d_in[1];   // (512, 512) f32
    const float* W    = (const float*)d_in[2];   // (64, 192) f32
    const float* bias = (const float*)d_in[3];   // (64,) f32
    float* out = (float*)d_out;                  // (16, 64, 512, 64) f32

    const int spmm_smem = 3 * STAGE;             // 178176
    cudaFuncSetAttribute(k_mix_tc, cudaFuncAttributeMaxDynamicSharedMemorySize, MIX_SMEM);
    cudaFuncSetAttribute(k_spmm_mma, cudaFuncAttributeMaxDynamicSharedMemorySize, spmm_smem);

    k_rownorm<<<N_, 256>>>(adj);
    k_norm2<<<dim3(32, 32), dim3(16, 16)>>>();
    k_wt<<<48, 256>>>(W);
    k_mix_tc<<<dim3(128, 2, 16), 256, MIX_SMEM>>>(x, bias, out);
    k_spmm_mma<<<dim3(2, 32, 16), 512, spmm_smem>>>(out);
}

// round 9
// speedup vs baseline: 5.9149x; 1.1437x over previous
#include <cuda_runtime.h>
#include <cuda_fp16.h>
#include <cstdint>

#define B_  16
#define N_  512
#define T_  64
#define OC_ 64

// ---------------- scratch (device globals; no runtime allocation) ----------
__device__ __align__(16) float  g_norm  [N_ * N_];      // fp32 (k_norm2 input)
__device__ __align__(16) __half g_normh [N_ * N_];      // fp16 (spmm A)
__device__ __align__(16) __half g_norm2h[N_ * N_];      // fp16 (spmm A)
__device__ __align__(16) __half g_Z1h[B_ * OC_ * N_ * T_];
__device__ __align__(16) __half g_Z2h[B_ * OC_ * N_ * T_];
__device__ __align__(16) __half g_Whf[192 * 64];        // [gc][c] fp16

// ======================= helpers ===========================================
__device__ __forceinline__ uint32_t smem_u32(const void* p) {
    uint32_t a;
    asm("{ .reg .u64 t; cvta.to.shared.u64 t, %1; cvt.u32.u64 %0, t; }"
        : "=r"(a) : "l"(p));
    return a;
}

#define CP16(dst, src) \
    asm volatile("cp.async.cg.shared.global [%0], [%1], 16;" \
                 :: "r"(dst), "l"(src) : "memory")
#define CP_COMMIT()  asm volatile("cp.async.commit_group;" ::: "memory")
#define CP_WAIT1()   asm volatile("cp.async.wait_group 1;" ::: "memory")
#define CP_WAIT0()   asm volatile("cp.async.wait_group 0;" ::: "memory")

#define MMA_F16(c, a0, a1, a2, a3, b0, b1) \
    asm volatile("mma.sync.aligned.m16n8k16.row.col.f32.f16.f16.f32 " \
                 "{%0,%1,%2,%3}, {%4,%5,%6,%7}, {%8,%9}, {%0,%1,%2,%3};" \
                 : "+f"((c)[0]), "+f"((c)[1]), "+f"((c)[2]), "+f"((c)[3]) \
                 : "r"(a0), "r"(a1), "r"(a2), "r"(a3), "r"(b0), "r"(b1))

__device__ __forceinline__ void ldsm_x4(uint32_t* r, uint32_t addr) {
    asm volatile("ldmatrix.sync.aligned.m8n8.x4.shared.b16 {%0,%1,%2,%3}, [%4];"
                 : "=r"(r[0]), "=r"(r[1]), "=r"(r[2]), "=r"(r[3]) : "r"(addr));
}
__device__ __forceinline__ void ldsm_x4t(uint32_t* r, uint32_t addr) {
    asm volatile("ldmatrix.sync.aligned.m8n8.x4.trans.shared.b16 {%0,%1,%2,%3}, [%4];"
                 : "=r"(r[0]), "=r"(r[1]), "=r"(r[2]), "=r"(r[3]) : "r"(addr));
}

// ---------------- kernel 0a: row-normalized adjacency ----------------------
__global__ void k_rownorm(const float* __restrict__ adj) {
    const int i = blockIdx.x;
    __shared__ float red[256];
    float s = 0.f;
    for (int j = threadIdx.x; j < N_; j += 256) s += adj[i * N_ + j];
    red[threadIdx.x] = s;
    __syncthreads();
    for (int off = 128; off > 0; off >>= 1) {
        if (threadIdx.x < off) red[threadIdx.x] += red[threadIdx.x + off];
        __syncthreads();
    }
    const float inv = 1.0f / (red[0] + 1e-6f);
    for (int j = threadIdx.x; j < N_; j += 256) {
        const float v = adj[i * N_ + j] * inv;
        g_norm [i * N_ + j] = v;
        g_normh[i * N_ + j] = __float2half_rn(v);
    }
}

// ---------------- kernel 0b: norm2 = norm @ norm (fp16 store) --------------
__global__ void k_norm2() {
    __shared__ float As[16][16];
    __shared__ float Bs[16][17];
    const int i = blockIdx.y * 16 + threadIdx.y;
    const int j = blockIdx.x * 16 + threadIdx.x;
    float acc = 0.f;
    for (int k0 = 0; k0 < N_; k0 += 16) {
        As[threadIdx.y][threadIdx.x] = g_norm[i * N_ + k0 + threadIdx.x];
        Bs[threadIdx.y][threadIdx.x] = g_norm[(k0 + threadIdx.y) * N_ + j];
        __syncthreads();
#pragma unroll
        for (int k = 0; k < 16; k++) acc += As[threadIdx.y][k] * Bs[k][threadIdx.x];
        __syncthreads();
    }
    g_norm2h[i * N_ + j] = __float2half_rn(acc);
}

// ---------------- kernel 0c: W -> fp16 [gc][c] layout -----------------------
__global__ void k_wt(const float* __restrict__ W) {
    const int idx = blockIdx.x * 256 + threadIdx.x;     // idx = gc*64 + c
    if (idx < 192 * 64) {
        const int gc = idx >> 6, c = idx & 63;
        const int grp = gc >> 6, oc = gc & 63;
        g_Whf[idx] = __float2half_rn(W[oc * 192 + grp * 64 + c]);
    }
}

// ---------------- kernel 1: channel mix via fp16 tensor cores ---------------
// CTA = (n4, cn, b). GEMM: M=256 (4n x 64t), N=96 (half of 192), K=64.
// Xh smem [c][m] halves (A via ldmatrix.trans); Wh [gc'][c] (B non-trans).
// Z0+bias (fp32) -> out; Z1/Z2 (fp16 RN) -> scratch.
#define XHST 264                               // Xh stride (halves)
#define WHST 72                                // Wh stride (halves)
#define SST  260
#define MIX_SMEM 49920                         // max(47616 data, 48*260*4 epi)

__global__ __launch_bounds__(256, 2) void k_mix_f16(const float* __restrict__ x,
                                                    const float* __restrict__ bias,
                                                    float* __restrict__ out) {
    extern __shared__ char dsm[];
    __half* Xh = (__half*)dsm;                       // [c=64][m=256]
    const uint32_t sb = smem_u32(dsm);
    const uint32_t wOff = 64 * XHST * 2;             // 33792
    const int n0 = blockIdx.x * 4, cn = blockIdx.y, b = blockIdx.z;
    const int tid = threadIdx.x, wid = tid >> 5, lane = tid & 31;
    const int u = wid >> 2, wi = wid & 3;
    const int g = lane >> 2, tg = lane & 3;
    const int q = lane >> 3, rr = lane & 7;

    // ---- W tile: 96 gc x 64 c halves via cp.async ----
#pragma unroll
    for (int r = 0; r < 3; r++) {
        const int i = r * 256 + tid;                 // < 768
        const int gcr = i >> 3, qq = i & 7;
        CP16(sb + wOff + (uint32_t)(gcr * WHST + qq * 8) * 2,
             g_Whf + (cn * 96 + gcr) * 64 + qq * 8);
    }
    CP_COMMIT();

    // ---- X tile: 64c x 256m fp32 -> fp16, [c][m] ----
#pragma unroll
    for (int r = 0; r < 16; r++) {
        const int i = r * 256 + tid;
        const int c = i >> 6, chunk = i & 63;
        const int nl = chunk >> 4, tq = chunk & 15;
        const float4 v = *(const float4*)(x + ((b * 64 + c) * 512 + n0 + nl) * 64 + tq * 4);
        union { __half2 h[2]; uint2 u2; } cv;
        cv.h[0] = __floats2half2_rn(v.x, v.y);
        cv.h[1] = __floats2half2_rn(v.z, v.w);
        *(uint2*)(Xh + c * XHST + nl * 64 + tq * 4) = cv.u2;
    }

    float acc[4][6][4];
#pragma unroll
    for (int mt = 0; mt < 4; mt++)
#pragma unroll
        for (int nt = 0; nt < 6; nt++)
#pragma unroll
            for (int r = 0; r < 4; r++) acc[mt][nt][r] = 0.f;

    CP_WAIT0();
    __syncthreads();

    // ---- mainloop: K=64 = 4 k16-steps ----
#pragma unroll
    for (int ks = 0; ks < 4; ks++) {
        uint32_t bf[3][4];
#pragma unroll
        for (int ntp = 0; ntp < 3; ntp++) {
            const int rowB = u * 48 + ntp * 16 + (q >> 1) * 8 + rr;   // gc
            const int colB = ks * 16 + (q & 1) * 8;                   // c
            ldsm_x4(bf[ntp], sb + wOff + (uint32_t)(rowB * WHST + colB) * 2);
        }
#pragma unroll
        for (int mt = 0; mt < 4; mt++) {
            const int rowA = ks * 16 + (q >> 1) * 8 + rr;             // c
            const int colA = wi * 64 + mt * 16 + (q & 1) * 8;         // m
            uint32_t af[4];
            ldsm_x4t(af, sb + (uint32_t)(rowA * XHST + colA) * 2);
#pragma unroll
            for (int nt = 0; nt < 6; nt++)
                MMA_F16(acc[mt][nt], af[0], af[1], af[2], af[3],
                        bf[nt >> 1][(nt & 1) * 2], bf[nt >> 1][(nt & 1) * 2 + 1]);
        }
    }

    // ---- epilogue: 2 passes through smem transpose Ss[oc'][m] ----
    float* Ss = (float*)dsm;
#pragma unroll
    for (int up = 0; up < 2; up++) {
        __syncthreads();
        if (u == up) {
#pragma unroll
            for (int mt = 0; mt < 4; mt++) {
                const int row = wi * 64 + mt * 16 + g;
#pragma unroll
                for (int nt = 0; nt < 6; nt++) {
                    const int col = nt * 8 + tg * 2;
                    Ss[col * SST + row]           = acc[mt][nt][0];
                    Ss[(col + 1) * SST + row]     = acc[mt][nt][1];
                    Ss[col * SST + row + 8]       = acc[mt][nt][2];
                    Ss[(col + 1) * SST + row + 8] = acc[mt][nt][3];
                }
            }
        }
        __syncthreads();
#pragma unroll
        for (int r = 0; r < 12; r++) {
            const int idx = r * 256 + tid;
            const int ocl = idx >> 6, mq = idx & 63;
            float4 v = *(const float4*)(Ss + ocl * SST + mq * 4);
            const int gc = cn * 96 + up * 48 + ocl;
            const int grp = gc >> 6, oc = gc & 63;
            const int base = ((b * 64 + oc) * 512 + n0 + (mq >> 4)) * 64 + (mq & 15) * 4;
            if (grp == 0) {
                const float bv = __ldg(bias + oc);
                v.x += bv; v.y += bv; v.z += bv; v.w += bv;
                *(float4*)(out + base) = v;
            } else {
                __half* dst = (grp == 1) ? g_Z1h : g_Z2h;
                union { __half2 h[2]; uint2 u2; } cv;
                cv.h[0] = __floats2half2_rn(v.x, v.y);
                cv.h[1] = __floats2half2_rn(v.z, v.w);
                *(uint2*)(dst + base) = cv.u2;
            }
        }
    }
}

// ---------------- kernel 2: out += norm@Z1 + norm2@Z2 (fp16 mma) -----------
// CTA = 128i x 64t x 2oc, 256 thr / 8 warps, 2 CTAs/SM.
// Warp = (wi: 2 x 64i) x (u: ocl = u>>1, t-half th = u&1) -> 64i x 32t.
// Kc=32, 2-stage cp.async; A stride 80B, B stride 144B (conflict-free ldsm).
#define AHST 40                                // A smem stride (halves)
#define BHST 72                                // B smem stride (halves)
#define A_SEC   (128 * AHST * 2)               // 10240 per matrix
#define A_BYTES (2 * A_SEC)                    // 20480
#define B_TILE  (32 * BHST * 2)                // 4608
#define STAGE   (A_BYTES + 4 * B_TILE)         // 38912
#define NCHUNK  16

__global__ __launch_bounds__(256, 2) void k_spmm_mma(float* __restrict__ out) {
    extern __shared__ char sm[];
    const uint32_t sb = smem_u32(sm);
    const int tid = threadIdx.x, wid = tid >> 5, lane = tid & 31;
    const int ih = blockIdx.x, ocp = blockIdx.y, b = blockIdx.z;
    const int i0g = ih * 128, oc0 = ocp * 2;
    const int wi = wid & 1, u = wid >> 1;
    const int ocl = u >> 1, th = u & 1;
    const int g = lane >> 2, tg = lane & 3;
    const int q = lane >> 3, rr = lane & 7;

    const __half* zb[4];
    zb[0] = g_Z1h + (size_t)(b * 64 + oc0) * 32768;
    zb[1] = g_Z2h + (size_t)(b * 64 + oc0) * 32768;
    zb[2] = g_Z1h + (size_t)(b * 64 + oc0 + 1) * 32768;
    zb[3] = g_Z2h + (size_t)(b * 64 + oc0 + 1) * 32768;

    float acc[4][4][4];
#pragma unroll
    for (int mt = 0; mt < 4; mt++)
#pragma unroll
        for (int nt = 0; nt < 4; nt++)
#pragma unroll
            for (int r = 0; r < 4; r++) acc[mt][nt][r] = 0.f;

    auto load_stage = [&](int c) {
        const int j0 = c * 32;
        const uint32_t st = sb + (uint32_t)(c & 1) * STAGE;
#pragma unroll
        for (int r = 0; r < 4; r++) {                    // A: 2 x 128 x 32h
            const int i = r * 256 + tid;
            const int m = i >> 9, rem = i & 511;
            const int row = rem >> 2, qq = rem & 3;
            CP16(st + (uint32_t)(m * A_SEC + row * (AHST * 2) + qq * 16),
                 (m ? g_norm2h : g_normh) + (i0g + row) * 512 + j0 + qq * 8);
        }
#pragma unroll
        for (int r = 0; r < 4; r++) {                    // B: 4 x 32 x 64h
            const int i = r * 256 + tid;
            const int tb = i >> 8, rem = i & 255;
            const int j = rem >> 3, qq = rem & 7;
            CP16(st + (uint32_t)(A_BYTES + tb * B_TILE + j * (BHST * 2) + qq * 16),
                 zb[tb] + (j0 + j) * 64 + qq * 8);
        }
        CP_COMMIT();
    };

    load_stage(0);

    for (int c = 0; c < NCHUNK; c++) {
        if (c + 1 < NCHUNK) { load_stage(c + 1); CP_WAIT1(); }
        else                { CP_WAIT0(); }
        __syncthreads();

        const uint32_t aA = sb + (uint32_t)(c & 1) * STAGE;
        const uint32_t aB = aA + A_BYTES;

#pragma unroll
        for (int ks = 0; ks < 2; ks++) {
            uint32_t bf[2][2][4];
#pragma unroll
            for (int m = 0; m < 2; m++) {
#pragma unroll
                for (int ntp = 0; ntp < 2; ntp++) {
                    const int rowB = ks * 16 + (q & 1) * 8 + rr;
                    const int colB = th * 32 + ntp * 16 + (q >> 1) * 8;
                    ldsm_x4t(bf[m][ntp],
                             aB + (uint32_t)((ocl * 2 + m) * 32 * BHST + rowB * BHST + colB) * 2);
                }
            }
#pragma unroll
            for (int mt = 0; mt < 4; mt++) {
#pragma unroll
                for (int m = 0; m < 2; m++) {
                    const int rowA = wi * 64 + mt * 16 + (q & 1) * 8 + rr;
                    const int colA = ks * 16 + (q >> 1) * 8;
                    uint32_t af[4];
                    ldsm_x4(af, aA + (uint32_t)(m * 128 * AHST + rowA * AHST + colA) * 2);
#pragma unroll
                    for (int nt = 0; nt < 4; nt++)
                        MMA_F16(acc[mt][nt], af[0], af[1], af[2], af[3],
                                bf[m][nt >> 1][(nt & 1) * 2],
                                bf[m][nt >> 1][(nt & 1) * 2 + 1]);
                }
            }
        }
        __syncthreads();
    }

    // ---- epilogue: RMW into out (holds Z0 + bias, fp32) ----
    float* obase = out + (((size_t)(b * 64 + oc0 + ocl) * 512) + i0g + wi * 64) * 64;
#pragma unroll
    for (int mt = 0; mt < 4; mt++) {
#pragma unroll
        for (int nt = 0; nt < 4; nt++) {
            const int r0 = mt * 16 + g, t0 = th * 32 + nt * 8 + tg * 2;
            float2* p0 = (float2*)(obase + r0 * 64 + t0);
            float2 v0 = *p0;
            v0.x += acc[mt][nt][0]; v0.y += acc[mt][nt][1];
            *p0 = v0;
            float2* p1 = (float2*)(obase + (r0 + 8) * 64 + t0);
            float2 v1 = *p1;
            v1.x += acc[mt][nt][2]; v1.y += acc[mt][nt][3];
            *p1 = v1;
        }
    }
}

// ---------------------------------------------------------------------------
extern "C" void kernel_launch(void* const* d_in, const int* in_sizes, int n_in,
                              void* d_out, int out_size) {
    const float* x    = (const float*)d_in[0];   // (16, 64, 512, 64) f32
    const float* adj  = (const float*)d_in[1];   // (512, 512) f32
    const float* W    = (const float*)d_in[2];   // (64, 192) f32
    const float* bias = (const float*)d_in[3];   // (64,) f32
    float* out = (float*)d_out;                  // (16, 64, 512, 64) f32

    const int spmm_smem = 2 * STAGE;             // 77824
    cudaFuncSetAttribute(k_mix_f16, cudaFuncAttributeMaxDynamicSharedMemorySize, MIX_SMEM);
    cudaFuncSetAttribute(k_spmm_mma, cudaFuncAttributeMaxDynamicSharedMemorySize, spmm_smem);

    k_rownorm<<<N_, 256>>>(adj);
    k_norm2<<<dim3(32, 32), dim3(16, 16)>>>();
    k_wt<<<48, 256>>>(W);
    k_mix_f16<<<dim3(128, 2, 16), 256, MIX_SMEM>>>(x, bias, out);
    k_spmm_mma<<<dim3(4, 32, 16), 256, spmm_smem>>>(out);
}